// round 4
// baseline (speedup 1.0000x reference)
#include <cuda_runtime.h>
#include <cuda_bf16.h>

// Problem constants (fixed by the reference setup_inputs)
#define NB    8      // batch
#define HH    28     // input H = W
#define NC    32     // channels (== warp size == one 128B line of floats)
#define HO    14     // output H = W
#define NOUT  196    // HO*HO
#define NIN   784    // HH*HH

#define WAVE  13     // j's gathered per batch (MLP depth per thread)

// ---------------------------------------------------------------------------
// Single fused kernel. grid = NB*NOUT blocks, 256 threads (8 warps).
// Block owns (b, i); lane = channel c. Each block:
//   1. computes its own row argmax (4 mu loads; mu is L2-resident, 3.2MB)
//   2. warp 0 writes mu_out[b,i,:]
//   3. per warp j-chunk: compute column argmax from mu on the fly,
//      gather Sigma[b, r_c, s_c(j), c] with WAVE-deep batched loads,
//      store coalesced 128B lines.
// All indexing is 32-bit (max element offset 157M < 2^31).
// ---------------------------------------------------------------------------
__global__ void __launch_bounds__(256)
fused_vdp_kernel(const float* __restrict__ mu,
                 const float* __restrict__ S,
                 float* __restrict__ outMu,
                 float* __restrict__ outS) {
    int b = blockIdx.x / NOUT;
    int i = blockIdx.x - b * NOUT;
    int c = threadIdx.x & 31;
    int w = threadIdx.x >> 5;  // 0..7

    const float* __restrict__ mub = mu + b * (NIN * NC);

    // ---- row argmax for this block's i (first-match, row-major order) ----
    {
        int oy = i / HO, ox = i - oy * HO;
        int iy = 2 * oy, ix = 2 * ox;
        const float* base = mub + (iy * HH + ix) * NC + c;
        float v00 = __ldg(base);
        float v01 = __ldg(base + NC);
        float v10 = __ldg(base + HH * NC);
        float v11 = __ldg(base + HH * NC + NC);
        float best = v00; int k = 0;
        if (v01 > best) { best = v01; k = 1; }
        if (v10 > best) { best = v10; k = 2; }
        if (v11 > best) { best = v11; k = 3; }
        int my_sidx = (iy + (k >> 1)) * HH + (ix + (k & 1));

        if (w == 0) outMu[(b * NOUT + i) * NC + c] = best;

        // fold row offset into the Sigma pointer (32-bit offsets are safe)
        S += b * (NIN * NIN * NC) + my_sidx * (NIN * NC) + c;
    }

    float* __restrict__ o = outS + (b * NOUT + i) * (NOUT * NC) + c;

    // even-ish split: warps 0-3 get 25 j's, warps 4-7 get 24 (= 196)
    int cnt  = (w < 4) ? 25 : 24;
    int jbeg = (w < 4) ? (w * 25) : (100 + (w - 4) * 24);

#pragma unroll 1
    for (int base = 0; base < cnt; base += WAVE) {
        int n = cnt - base; if (n > WAVE) n = WAVE;

        // 1) column argmax for this wave of j's (mu loads are L2 hits)
        int s[WAVE];
#pragma unroll
        for (int t = 0; t < WAVE; t++) {
            if (t < n) {
                int j  = jbeg + base + t;
                int jy = j / HO, jx = j - jy * HO;
                int y0 = 2 * jy, x0 = 2 * jx;
                const float* p = mub + (y0 * HH + x0) * NC + c;
                float m00 = __ldg(p);
                float m01 = __ldg(p + NC);
                float m10 = __ldg(p + HH * NC);
                float m11 = __ldg(p + HH * NC + NC);
                float mb = m00; int k = 0;
                if (m01 > mb) { mb = m01; k = 1; }
                if (m10 > mb) { mb = m10; k = 2; }
                if (m11 > mb) { mb = m11; k = 3; }
                s[t] = (y0 + (k >> 1)) * HH + (x0 + (k & 1));
            }
        }

        // 2) batched gathers (evict-first: zero reuse)
        float v[WAVE];
#pragma unroll
        for (int t = 0; t < WAVE; t++)
            if (t < n) v[t] = __ldcs(S + s[t] * NC);

        // 3) coalesced streaming stores
#pragma unroll
        for (int t = 0; t < WAVE; t++)
            if (t < n) __stcs(o + (jbeg + base + t) * NC, v[t]);
    }
}

// ---------------------------------------------------------------------------
// Launch: d_in[0] = mu_in [8,28,28,32] f32, d_in[1] = Sigma_in [8,784,784,32] f32
// d_out = mu_out (50176 floats) followed by Sigma_out (9834496 floats).
// ---------------------------------------------------------------------------
extern "C" void kernel_launch(void* const* d_in, const int* in_sizes, int n_in,
                              void* d_out, int out_size) {
    const float* mu    = (const float*)d_in[0];
    const float* Sigma = (const float*)d_in[1];
    float* out   = (float*)d_out;
    float* outMu = out;
    float* outS  = out + NB * NOUT * NC;   // 50176

    fused_vdp_kernel<<<NB * NOUT, 256>>>(mu, Sigma, outMu, outS);
}

// round 5
// speedup vs baseline: 1.0544x; 1.0544x over previous
#include <cuda_runtime.h>
#include <cuda_bf16.h>

// Problem constants (fixed by the reference setup_inputs)
#define NB    8      // batch
#define HH    28     // input H = W
#define NC    32     // channels (== warp size == one 128B line of floats)
#define HO    14     // output H = W
#define NOUT  196    // HO*HO
#define NIN   784    // HH*HH

// Scratch: flat input spatial index of the per-(b,i,c) argmax,
// laid out [b][i][c] so a warp (lane=c) reads one coalesced line per i.
__device__ int g_sidx[NB * NOUT * NC];

// ---------------------------------------------------------------------------
// Kernel A: 2x2 max-pool argmax -> mu_out + gather index.
// One thread per (b, oy, ox, c); 50176 threads total.
// ---------------------------------------------------------------------------
__global__ void pool_idx_kernel(const float* __restrict__ mu,
                                float* __restrict__ out_mu) {
    int t = blockIdx.x * blockDim.x + threadIdx.x;
    if (t < NB * NOUT * NC) {
        int c = t & (NC - 1);
        int p = t >> 5;            // b*196 + i
        int i = p % NOUT;
        int oy = i / HO, ox = i - oy * HO;
        int iy = 2 * oy, ix = 2 * ox;
        int b = p / NOUT;

        const float* base = mu + ((b * HH + iy) * HH + ix) * NC + c;
        float v00 = base[0];
        float v01 = base[NC];
        float v10 = base[HH * NC];
        float v11 = base[HH * NC + NC];

        // first-match argmax over row-major order (0,0),(0,1),(1,0),(1,1)
        float best = v00; int k = 0;
        if (v01 > best) { best = v01; k = 1; }
        if (v10 > best) { best = v10; k = 2; }
        if (v11 > best) { best = v11; k = 3; }
        int dy = k >> 1, dx = k & 1;

        out_mu[t] = best;
        g_sidx[t] = (iy + dy) * HH + (ix + dx);   // flat input spatial index
    }
    // PDL: allow the dependent gather kernel to begin its prologue early.
    cudaTriggerProgrammaticLaunchCompletion();
}

// ---------------------------------------------------------------------------
// Kernel B: Sigma double-gather.
// grid.x = NB*NOUT blocks; block = 224 threads (7 warps). Block owns (b, i);
// lane = channel c. 196 j's split EXACTLY 28 per warp; each warp runs two
// predicate-free waves of 14 batched independent gathers (MLP=14/thread),
// then coalesced 128B streaming stores. All offsets 32-bit.
// ---------------------------------------------------------------------------
#define WAVE 14

__global__ void __launch_bounds__(224)
sigma_gather_kernel(const float* __restrict__ S, float* __restrict__ outS) {
    int b = blockIdx.x / NOUT;
    int i = blockIdx.x - b * NOUT;
    int c = threadIdx.x & 31;
    int w = threadIdx.x >> 5;  // 0..6
    int jbeg = w * 28;         // exactly 28 j's per warp

    float* __restrict__ o = outS + (b * NOUT + i) * (NOUT * NC) + c;
    const int* __restrict__ sj_base = &g_sidx[b * NOUT * NC + c];

    // Wait for pool_idx_kernel's g_sidx writes (PDL dependency).
    cudaGridDependencySynchronize();

    int my_sidx = g_sidx[(b * NOUT + i) * NC + c];
    const float* __restrict__ Sp =
        S + b * (NIN * NIN * NC) + my_sidx * (NIN * NC) + c;

#pragma unroll 1
    for (int half = 0; half < 2; half++) {
        int base = jbeg + half * WAVE;
        int sj[WAVE];
        float v[WAVE];
#pragma unroll
        for (int t = 0; t < WAVE; t++)
            sj[t] = __ldg(sj_base + (base + t) * NC);
#pragma unroll
        for (int t = 0; t < WAVE; t++)
            v[t] = __ldcs(Sp + sj[t] * NC);
#pragma unroll
        for (int t = 0; t < WAVE; t++)
            __stcs(o + (base + t) * NC, v[t]);
    }
}

// ---------------------------------------------------------------------------
// Launch: d_in[0] = mu_in [8,28,28,32] f32, d_in[1] = Sigma_in [8,784,784,32] f32
// d_out = mu_out (50176 floats) followed by Sigma_out (9834496 floats).
// ---------------------------------------------------------------------------
extern "C" void kernel_launch(void* const* d_in, const int* in_sizes, int n_in,
                              void* d_out, int out_size) {
    const float* mu    = (const float*)d_in[0];
    const float* Sigma = (const float*)d_in[1];
    float* out   = (float*)d_out;
    float* outMu = out;
    float* outS  = out + NB * NOUT * NC;   // 50176

    pool_idx_kernel<<<(NB * NOUT * NC + 255) / 256, 256>>>(mu, outMu);

    // Programmatic dependent launch: B's prologue overlaps A + launch latency.
    cudaLaunchAttribute attrs[1];
    attrs[0].id = cudaLaunchAttributeProgrammaticStreamSerialization;
    attrs[0].val.programmaticStreamSerializationAllowed = 1;
    cudaLaunchConfig_t cfg = {};
    cfg.gridDim  = dim3(NB * NOUT, 1, 1);
    cfg.blockDim = dim3(224, 1, 1);
    cfg.dynamicSmemBytes = 0;
    cfg.stream = 0;
    cfg.attrs = attrs;
    cfg.numAttrs = 1;
    cudaLaunchKernelEx(&cfg, sigma_gather_kernel, Sigma, outS);
}